// round 15
// baseline (speedup 1.0000x reference)
#include <cuda_runtime.h>
#include <cuda_fp16.h>
#include <math.h>

#define S       64
#define LPREV   512
#define NF      193
#define NFRAMES 100
#define BATCH   64
#define NTH     512
#define NBT     (BATCH * NFRAMES)   // 6400

// ---------------- scratch (static device allocations) ----------------
__device__ float  g_X [NBT * 256];
__device__ float  g_H1[NBT * 256];
__device__ float  g_H2[NBT * 256];
__device__ float  g_C [NBT * 512];
__device__ float  g_fwpre[NBT * 4 * 64];
__device__ int    g_period[NBT];
__device__ __half g_hWsd[128 * 320];

__device__ __forceinline__ float sigm(float x)   { return __fdividef(1.f, 1.f + __expf(-x)); }
__device__ __forceinline__ float tanh_f(float x) { return fmaf(2.f, __fdividef(1.f, 1.f + __expf(-2.f * x)), -1.f); }
__device__ __forceinline__ float red8(float v) {
    v += __shfl_xor_sync(0xffffffffu, v, 1);
    v += __shfl_xor_sync(0xffffffffu, v, 2);
    v += __shfl_xor_sync(0xffffffffu, v, 4);
    return v;
}
// half2 MAC of 8 fp16 weights (uint4) with 8 fp16 activations (uint4)
__device__ __forceinline__ __half2 dot8hh(uint4 w, uint4 x, __half2 acc) {
    const __half2* wh = reinterpret_cast<const __half2*>(&w);
    const __half2* xh = reinterpret_cast<const __half2*>(&x);
    acc = __hfma2(wh[0], xh[0], acc);
    acc = __hfma2(wh[1], xh[1], acc);
    acc = __hfma2(wh[2], xh[2], acc);
    acc = __hfma2(wh[3], xh[3], acc);
    return acc;
}
__device__ __forceinline__ float hsum2f(__half2 a) {
    float2 f = __half22float2(a);
    return f.x + f.y;
}
// dot of 8 fp32 weights (two float4) with 8 fp32 inputs (two float4)
__device__ __forceinline__ float dot8f(float4 wa, float4 wb, float4 xa, float4 xb) {
    float a = wa.x * xa.x;
    a = fmaf(wa.y, xa.y, a);
    a = fmaf(wa.z, xa.z, a); a = fmaf(wa.w, xa.w, a);
    a = fmaf(wb.x, xb.x, a); a = fmaf(wb.y, xb.y, a);
    a = fmaf(wb.z, xb.z, a); a = fmaf(wb.w, xb.w, a);
    return a;
}
// pack 8 consecutive fp32 -> uint4 of 8 fp16
__device__ __forceinline__ uint4 pack8(const float* __restrict__ s) {
    union { uint4 u; __half2 h[4]; } r;
    r.h[0] = __floats2half2_rn(__ldg(&s[0]), __ldg(&s[1]));
    r.h[1] = __floats2half2_rn(__ldg(&s[2]), __ldg(&s[3]));
    r.h[2] = __floats2half2_rn(__ldg(&s[4]), __ldg(&s[5]));
    r.h[3] = __floats2half2_rn(__ldg(&s[6]), __ldg(&s[7]));
    return r.u;
}

// ---------------- prep kernels ----------------
// build_x also converts Wsd -> fp16 so launch #6 is fargan_kernel (ncu -s 5 -c 1).
__global__ void build_x_kernel(const float* __restrict__ feats,
                               const float* __restrict__ glob,
                               const float* __restrict__ Wsd)
{
    const int bt = blockIdx.x;
    const int b = bt / NFRAMES, t = bt % NFRAMES;
    const float* fb = feats + (long)b * NF * NFRAMES;
    for (int i = threadIdx.x; i < 192; i += blockDim.x)
        g_X[bt * 256 + i] = fb[i * NFRAMES + t];
    for (int i = threadIdx.x; i < 64; i += blockDim.x)
        g_X[bt * 256 + 192 + i] = glob[b * 64 + i];
    if (threadIdx.x == 0)
        g_period[bt] = (int)lrintf(fb[192 * NFRAMES + t]);
    if (bt < 640) {
        int i = bt * 64 + threadIdx.x;
        if (threadIdx.x < 64 && i < 128 * 320)
            g_hWsd[i] = __float2half(Wsd[i]);
    }
}

// C[M,N] = tanh(A[M,K] @ W[N,K]^T); tiles 64x64x64
__global__ __launch_bounds__(256)
void gemm_tanh_kernel(const float* __restrict__ Wt, int layer, int N, int K)
{
    const float* A = (layer == 0) ? g_X : (layer == 1) ? g_H1 : g_H2;
    float*       C = (layer == 0) ? g_H1 : (layer == 1) ? g_H2 : g_C;

    __shared__ float As[64][68];
    __shared__ float Ws[64][68];

    const int tid = threadIdx.x;
    const int m0 = blockIdx.y * 64, n0 = blockIdx.x * 64;
    const int lr = tid >> 2, lc = tid & 3;
    const int ty = tid >> 4, tx = tid & 15;

    float acc[4][4] = {};

    for (int k0 = 0; k0 < K; k0 += 64) {
        const float4* Arow = (const float4*)(A  + (long)(m0 + lr) * K + k0);
        const float4* Wrow = (const float4*)(Wt + (long)(n0 + lr) * K + k0);
        #pragma unroll
        for (int jj = 0; jj < 4; jj++) {
            float4 av = __ldg(&Arow[lc * 4 + jj]);
            float4 wv = __ldg(&Wrow[lc * 4 + jj]);
            int kk = lc * 16 + jj * 4;
            As[kk + 0][lr] = av.x; As[kk + 1][lr] = av.y;
            As[kk + 2][lr] = av.z; As[kk + 3][lr] = av.w;
            Ws[kk + 0][lr] = wv.x; Ws[kk + 1][lr] = wv.y;
            Ws[kk + 2][lr] = wv.z; Ws[kk + 3][lr] = wv.w;
        }
        __syncthreads();
        #pragma unroll
        for (int kk = 0; kk < 64; kk++) {
            float4 a = *(const float4*)&As[kk][ty * 4];
            float4 w = *(const float4*)&Ws[kk][tx * 4];
            acc[0][0] = fmaf(a.x, w.x, acc[0][0]); acc[0][1] = fmaf(a.x, w.y, acc[0][1]);
            acc[0][2] = fmaf(a.x, w.z, acc[0][2]); acc[0][3] = fmaf(a.x, w.w, acc[0][3]);
            acc[1][0] = fmaf(a.y, w.x, acc[1][0]); acc[1][1] = fmaf(a.y, w.y, acc[1][1]);
            acc[1][2] = fmaf(a.y, w.z, acc[1][2]); acc[1][3] = fmaf(a.y, w.w, acc[1][3]);
            acc[2][0] = fmaf(a.z, w.x, acc[2][0]); acc[2][1] = fmaf(a.z, w.y, acc[2][1]);
            acc[2][2] = fmaf(a.z, w.z, acc[2][2]); acc[2][3] = fmaf(a.z, w.w, acc[2][3]);
            acc[3][0] = fmaf(a.w, w.x, acc[3][0]); acc[3][1] = fmaf(a.w, w.y, acc[3][1]);
            acc[3][2] = fmaf(a.w, w.z, acc[3][2]); acc[3][3] = fmaf(a.w, w.w, acc[3][3]);
        }
        __syncthreads();
    }
    #pragma unroll
    for (int i = 0; i < 4; i++)
        #pragma unroll
        for (int j = 0; j < 4; j++)
            C[(long)(m0 + ty * 4 + i) * N + n0 + tx * 4 + j] = tanh_f(acc[i][j]);
}

// fwpre[bt][k][j] = Wfw[j,0:128] @ feat2s(bt,k) + Wfw[j,260:388] @ sfw(bt,k)
__global__ __launch_bounds__(256)
void fwpre_kernel(const float* __restrict__ Wfw)
{
    const int bt = blockIdx.x;
    const int t  = bt % NFRAMES;
    const int tid = threadIdx.x;
    __shared__ float sc[512], sp[512];
    for (int i = tid; i < 512; i += 256) {
        sc[i] = g_C[(long)bt * 512 + i];
        sp[i] = (t > 0) ? g_C[(long)(bt - 1) * 512 + i] : 0.f;
    }
    __syncthreads();
    const int p = tid & 3, row = tid >> 2;
    const float* wr = Wfw + row * 388;
    #pragma unroll
    for (int k = 0; k < 4; k++) {
        const float* sfw = (k == 0) ? sp : sc;
        const int ksf = (k == 0) ? 3 : (k - 1);
        float acc = 0.f;
        #pragma unroll 8
        for (int mm = 0; mm < 32; mm++) {
            int m = p * 32 + mm;
            acc = fmaf(__ldg(&wr[m]),       sc[4 * m + k],    acc);
            acc = fmaf(__ldg(&wr[260 + m]), sfw[4 * m + ksf], acc);
        }
        acc += __shfl_xor_sync(0xffffffffu, acc, 1);
        acc += __shfl_xor_sync(0xffffffffu, acc, 2);
        if (p == 0) g_fwpre[((long)bt * 4 + k) * 64 + row] = acc;
    }
}

// ---------------- serial recurrence ----------------

#define DYN_H16   (3 * 192 * 128 + 3 * 192 * 64)   // Wih x3 + Whh x3 = 110592 halfs
#define DYN_BYTES (DYN_H16 * 2)                    // 221184 B

__global__ __launch_bounds__(NTH, 1)
void fargan_kernel(const float* __restrict__ prev0,
                   const float* __restrict__ Wfw,     // (64,388)
                   const float* __restrict__ Wfw_g,   // (64,64)
                   const float* __restrict__ Wih1,    // (192,128)
                   const float* __restrict__ Whh1,    // (192,64)
                   const float* __restrict__ Wih2,
                   const float* __restrict__ Whh2,
                   const float* __restrict__ Wih3,
                   const float* __restrict__ Whh3,
                   const float* __restrict__ Wg1,     // (64,64)
                   const float* __restrict__ Wg2,
                   const float* __restrict__ Wg3,
                   const float* __restrict__ Wsg,     // (128,128)
                   const float* __restrict__ Wout,    // (64,128)
                   float* __restrict__ outp)          // (B, 25600)
{
    const int b   = blockIdx.x;
    const int tid = threadIdx.x;
    const int p   = tid & 7;        // 8 threads per row
    const int r0  = tid >> 3;       // 64 rows per pass

    extern __shared__ __half dynh[];
    __half* sWih = dynh;                 // 3 x 192 x 128
    __half* sWhh = dynh + 3 * 192 * 128; // 3 x 192 x 64

    __shared__ __align__(16) float  ring[LPREV];
    __shared__ __align__(16) float  st[2][3][S];     // fp32 recurrent state (double-buffered)
    __shared__ __align__(16) __half sth[2][3][S];    // half copy for Whh dots
    __shared__ __align__(16) float  subin[160];      // fp32 [prev_sub(64) | lookback(68) | zero pad]
    __shared__ __align__(16) float  fwv[S];          // fp32 (feeds fp32 gate dot)
    __shared__ __align__(16) __half xcath[2 * S];    // half GRU input [fw/o | psub]
    __shared__ __align__(16) __half skiph[5 * S];    // half [o1|o2|o3|fw|psub]
    __shared__ __align__(16) __half sdvh[2 * S];
    __shared__ __align__(16) __half sovh[2 * S];
    __shared__ __align__(16) float  fwp4[256];
    __shared__ __align__(16) float  ghs[3 * 192];    // hoisted Whh@st results [L][it][row]
    __shared__ int period_sh;

    // ---- one-time: stage Wih / Whh as fp16 into smem ----
    {
        const float* src[3] = { Wih1, Wih2, Wih3 };
        #pragma unroll
        for (int m = 0; m < 3; m++)
            for (int i = tid; i < 192 * 128; i += NTH)
                sWih[m * 192 * 128 + i] = __float2half(__ldg(&src[m][i]));
        const float* srh[3] = { Whh1, Whh2, Whh3 };
        #pragma unroll
        for (int m = 0; m < 3; m++)
            for (int i = tid; i < 192 * 64; i += NTH)
                sWhh[m * 192 * 64 + i] = __float2half(__ldg(&srh[m][i]));
    }

    // ---- persistent register weight caches ----
    // Wfw2 (cols [128,264) of Wfw) as 5 strided float4 chunks
    float4 rfw2v[5];
    #pragma unroll
    for (int j = 0; j < 5; j++) {
        int c = p + 8 * j;
        float e[4];
        #pragma unroll
        for (int q = 0; q < 4; q++) {
            int col = 4 * c + q;
            e[q] = (col < 132) ? __ldg(&Wfw[r0 * 388 + 128 + col]) : 0.f;
        }
        rfw2v[j] = make_float4(e[0], e[1], e[2], e[3]);
    }
    // gates (Wg1,Wg2,Wg3,Wfwg): fp32, row r0, cols [8p, 8p+8)
    float4 rgf[4][2];
    {
        const float* gsrc[4] = { Wg1, Wg2, Wg3, Wfw_g };
        #pragma unroll
        for (int m = 0; m < 4; m++) {
            const float4* w = (const float4*)(gsrc[m] + r0 * 64 + 8 * p);
            rgf[m][0] = __ldg(&w[0]);
            rgf[m][1] = __ldg(&w[1]);
        }
    }
    // Wsg: 128x128 fp16, rows r0 and r0+64, chunks p and p+8
    uint4 rsgh[2][2];
    #pragma unroll
    for (int it = 0; it < 2; it++) {
        rsgh[it][0] = pack8(Wsg + (r0 + 64 * it) * 128 + 8 * p);
        rsgh[it][1] = pack8(Wsg + (r0 + 64 * it) * 128 + 8 * (p + 8));
    }
    // Wout: 64x128 fp16, row r0, chunks p and p+8
    uint4 routh[2];
    routh[0] = pack8(Wout + r0 * 128 + 8 * p);
    routh[1] = pack8(Wout + r0 * 128 + 8 * (p + 8));

    // Wsd chunk pointers
    const uint4* wsd0 = (const uint4*)(g_hWsd + r0 * 320) + p;
    const uint4* wsd1 = (const uint4*)(g_hWsd + (r0 + 64) * 320) + p;

    // ---- init state ----
    for (int i = tid; i < LPREV; i += NTH) ring[i] = prev0[b * LPREV + i];
    if (tid < 3 * S) {
        st[0][tid >> 6][tid & 63] = 0.f;
        sth[0][tid >> 6][tid & 63] = __half(0.f);
    }
    if (tid >= 132 && tid < 160) subin[tid] = 0.f;
    if (tid < 64) {
        float v = prev0[b * LPREV + 448 + tid];
        subin[tid] = v;
        __half hv = __float2half(v);
        skiph[256 + tid] = hv;
        xcath[64 + tid] = hv;
    }
    int head = 0;
    int pb = 0;
    __syncthreads();

    const __half2 hz = __floats2half2_rn(0.f, 0.f);

    for (int tf = 0; tf < NFRAMES; tf++) {
        const int bt = b * NFRAMES + tf;
        if (tid < 256) fwp4[tid] = __ldg(&g_fwpre[(long)bt * 256 + tid]);
        if (tid == 0) period_sh = __ldg(&g_period[bt]);
        __syncthreads();
        const int period = period_sh;

        for (int k = 0; k < 4; k++) {
            float sd0 = 0.f, sd1 = 0.f;

            // ---- A: lookback only ----
            if (tid >= 64 && tid < 132) {
                int i = tid - 64;
                int idx = LPREV - period + i - 2;
                if (idx >= LPREV) idx -= period;
                subin[tid] = ring[(head + idx) & 511];
            }
            __syncthreads();

            // ---- B: fwraw + Wsd psub part + gh1 hoist ----
            float fwreg;
            {
                uint4 w0 = __ldg(wsd0 + 32), w1 = __ldg(wsd1 + 32);
                const float4* xs4 = (const float4*)subin;
                float a = 0.f;
                #pragma unroll
                for (int j = 0; j < 5; j++) {
                    float4 w = rfw2v[j];
                    float4 x = xs4[p + 8 * j];
                    a = fmaf(w.x, x.x, a); a = fmaf(w.y, x.y, a);
                    a = fmaf(w.z, x.z, a); a = fmaf(w.w, x.w, a);
                }
                fwreg = tanh_f(red8(a) + fwp4[k * 64 + r0]);
                if (p == 0) fwv[r0] = fwreg;
                uint4 xs = ((const uint4*)(skiph + 256))[p];
                sd0 += hsum2f(dot8hh(w0, xs, hz));
                sd1 += hsum2f(dot8hh(w1, xs, hz));

                // gh1: Whh1 @ st[pb][0]  (read-only this subframe)
                uint4 sv = ((const uint4*)sth[pb][0])[p];
                #pragma unroll
                for (int it = 0; it < 3; it++) {
                    const uint4* wh = (const uint4*)(sWhh + (r0 + (it << 6)) * 64);
                    float g = red8(hsum2f(dot8hh(wh[p], sv, hz)));
                    if (p == 0) ghs[(it << 6) + r0] = g;
                }
            }
            __syncthreads();

            // ---- C: fw gate + gh2 hoist ----
            {
                const float4* x = (const float4*)fwv;
                float acc = red8(dot8f(rgf[3][0], rgf[3][1], x[2 * p], x[2 * p + 1]));
                fwreg = fwreg * sigm(acc);
                if (p == 0) {
                    __half hv = __float2half(fwreg);
                    skiph[192 + r0] = hv;
                    xcath[r0] = hv;
                }
                // gh2: Whh2 @ st[pb][1]
                uint4 sv = ((const uint4*)sth[pb][1])[p];
                const __half* WH = sWhh + 192 * 64;
                #pragma unroll
                for (int it = 0; it < 3; it++) {
                    const uint4* wh = (const uint4*)(WH + (r0 + (it << 6)) * 64);
                    float g = red8(hsum2f(dot8hh(wh[p], sv, hz)));
                    if (p == 0) ghs[192 + (it << 6) + r0] = g;
                }
            }
            __syncthreads();

            // ---- 3 x (GRU fused + GLU fused); gh from ghs ----
            #pragma unroll
            for (int L = 0; L < 3; L++) {
                const __half* WI = sWih + L * 192 * 128;
                const float* sto = st[pb][L];
                float* stn = st[pb ^ 1][L];
                __half* stnh = sth[pb ^ 1][L];
                float streg;
                {
                    const int m = (L == 0) ? 3 : (L - 1);
                    uint4 w0 = __ldg(wsd0 + 8 * m), w1 = __ldg(wsd1 + 8 * m);

                    const uint4* xh = (const uint4*)xcath;
                    uint4 xa = xh[p], xb = xh[p + 8];
                    float gi[3];
                    #pragma unroll
                    for (int it = 0; it < 3; it++) {
                        const uint4* wi = (const uint4*)(WI + (r0 + (it << 6)) * 128);
                        __half2 acc = dot8hh(wi[p], xa, hz);
                        acc = dot8hh(wi[p + 8], xb, acc);
                        gi[it] = red8(hsum2f(acc));
                    }
                    float g0 = ghs[L * 192 + r0];
                    float g1 = ghs[L * 192 + 64 + r0];
                    float g2 = ghs[L * 192 + 128 + r0];
                    float r = sigm(gi[0] + g0);
                    float z = sigm(gi[1] + g1);
                    float n = tanh_f(gi[2] + r * g2);
                    streg = (1.f - z) * n + z * sto[r0];
                    if (p == 0) {
                        stn[r0] = streg;
                        stnh[r0] = __float2half(streg);
                    }

                    uint4 xm = ((const uint4*)(skiph + 64 * m))[p];
                    sd0 += hsum2f(dot8hh(w0, xm, hz));
                    sd1 += hsum2f(dot8hh(w1, xm, hz));
                }
                __syncthreads();
                {
                    const float4* x = (const float4*)stn;
                    float acc = red8(dot8f(rgf[L][0], rgf[L][1], x[2 * p], x[2 * p + 1]));
                    float v = streg * sigm(acc);
                    if (p == 0) {
                        __half hv = __float2half(v);
                        skiph[64 * L + r0] = hv;
                        if (L < 2) xcath[r0] = hv;
                    }
                    if (L == 0) {
                        // gh3 hoist: Whh3 @ st[pb][2] (still unmodified)
                        uint4 sv = ((const uint4*)sth[pb][2])[p];
                        const __half* WH = sWhh + 2 * 192 * 64;
                        #pragma unroll
                        for (int it = 0; it < 3; it++) {
                            const uint4* wh = (const uint4*)(WH + (r0 + (it << 6)) * 64);
                            float g = red8(hsum2f(dot8hh(wh[p], sv, hz)));
                            if (p == 0) ghs[384 + (it << 6) + r0] = g;
                        }
                    }
                }
                __syncthreads();
            }

            // ---- J (mini): add o3 part, finalize sdv ----
            float sdva[2];
            {
                uint4 w0 = __ldg(wsd0 + 16), w1 = __ldg(wsd1 + 16);
                uint4 xm = ((const uint4*)(skiph + 128))[p];
                sd0 += hsum2f(dot8hh(w0, xm, hz));
                sd1 += hsum2f(dot8hh(w1, xm, hz));
                sdva[0] = tanh_f(red8(sd0));
                sdva[1] = tanh_f(red8(sd1));
                if (p == 0) {
                    sdvh[r0] = __float2half(sdva[0]);
                    sdvh[64 + r0] = __float2half(sdva[1]);
                }
            }
            __syncthreads();

            // ---- K: sov = sdv * sigm(Wsg @ sdv) ----
            {
                const uint4* xh = (const uint4*)sdvh;
                uint4 xa = xh[p], xb = xh[p + 8];
                #pragma unroll
                for (int it = 0; it < 2; it++) {
                    __half2 acc = dot8hh(rsgh[it][0], xa, hz);
                    acc = dot8hh(rsgh[it][1], xb, acc);
                    float a = red8(hsum2f(acc));
                    if (p == 0) sovh[r0 + 64 * it] = __float2half(sdva[it] * sigm(a));
                }
            }
            __syncthreads();

            // ---- L: out = tanh(Wout @ sov); emit + ring + psub seed ----
            {
                const uint4* xh = (const uint4*)sovh;
                __half2 acc = dot8hh(routh[0], xh[p], hz);
                acc = dot8hh(routh[1], xh[p + 8], acc);
                float out = tanh_f(red8(hsum2f(acc)));
                if (p == 0) {
                    outp[(long)b * (NFRAMES * 4 * S) + tf * (4 * S) + k * S + r0] = out;
                    ring[(head + r0) & 511] = out;
                    subin[r0] = out;
                    __half hv = __float2half(out);
                    skiph[256 + r0] = hv;
                    xcath[64 + r0] = hv;
                }
            }
            head = (head + 64) & 511;
            pb ^= 1;
            __syncthreads();
        }
    }
}

extern "C" void kernel_launch(void* const* d_in, const int* in_sizes, int n_in,
                              void* d_out, int out_size)
{
    const float* feats = (const float*)d_in[0];
    const float* glob  = (const float*)d_in[1];
    const float* prev0 = (const float*)d_in[2];
    const float* Wc1   = (const float*)d_in[3];
    const float* Wc2   = (const float*)d_in[4];
    const float* Wc3   = (const float*)d_in[5];
    const float* Wfw   = (const float*)d_in[6];
    const float* Wfw_g = (const float*)d_in[7];
    const float* Wih1  = (const float*)d_in[8];
    const float* Whh1  = (const float*)d_in[9];
    const float* Wih2  = (const float*)d_in[10];
    const float* Whh2  = (const float*)d_in[11];
    const float* Wih3  = (const float*)d_in[12];
    const float* Whh3  = (const float*)d_in[13];
    const float* Wg1   = (const float*)d_in[14];
    const float* Wg2   = (const float*)d_in[15];
    const float* Wg3   = (const float*)d_in[16];
    const float* Wsg   = (const float*)d_in[17];
    const float* Wsd   = (const float*)d_in[18];
    const float* Wout  = (const float*)d_in[19];
    float* outp = (float*)d_out;

    static bool attr_set = false;
    if (!attr_set) {
        cudaFuncSetAttribute(fargan_kernel,
                             cudaFuncAttributeMaxDynamicSharedMemorySize, DYN_BYTES);
        attr_set = true;
    }

    build_x_kernel<<<NBT, 64>>>(feats, glob, Wsd);
    gemm_tanh_kernel<<<dim3(4, 100), 256>>>(Wc1, 0, 256, 256);
    gemm_tanh_kernel<<<dim3(4, 100), 256>>>(Wc2, 1, 256, 256);
    gemm_tanh_kernel<<<dim3(8, 100), 256>>>(Wc3, 2, 512, 256);
    fwpre_kernel<<<NBT, 256>>>(Wfw);
    fargan_kernel<<<BATCH, NTH, DYN_BYTES>>>(prev0,
                                  Wfw, Wfw_g,
                                  Wih1, Whh1, Wih2, Whh2, Wih3, Whh3,
                                  Wg1, Wg2, Wg3, Wsg, Wout, outp);
}

// round 16
// speedup vs baseline: 1.7437x; 1.7437x over previous
#include <cuda_runtime.h>
#include <cuda_fp16.h>
#include <math.h>

#define S       64
#define LPREV   512
#define NF      193
#define NFRAMES 100
#define BATCH   64
#define NTH     512
#define NBT     (BATCH * NFRAMES)   // 6400

// ---------------- scratch (static device allocations) ----------------
__device__ float  g_X [NBT * 256];
__device__ float  g_H1[NBT * 256];
__device__ float  g_H2[NBT * 256];
__device__ float  g_C [NBT * 512];
__device__ float  g_fwpre[NBT * 4 * 64];
__device__ int    g_period[NBT];
__device__ __half g_hWsd[128 * 320];

__device__ __forceinline__ float sigm(float x)   { return __fdividef(1.f, 1.f + __expf(-x)); }
__device__ __forceinline__ float tanh_f(float x) { return fmaf(2.f, __fdividef(1.f, 1.f + __expf(-2.f * x)), -1.f); }
__device__ __forceinline__ float red8(float v) {
    v += __shfl_xor_sync(0xffffffffu, v, 1);
    v += __shfl_xor_sync(0xffffffffu, v, 2);
    v += __shfl_xor_sync(0xffffffffu, v, 4);
    return v;
}
// half2 MAC of 8 fp16 weights (uint4) with 8 fp16 activations (uint4)
__device__ __forceinline__ __half2 dot8hh(uint4 w, uint4 x, __half2 acc) {
    const __half2* wh = reinterpret_cast<const __half2*>(&w);
    const __half2* xh = reinterpret_cast<const __half2*>(&x);
    acc = __hfma2(wh[0], xh[0], acc);
    acc = __hfma2(wh[1], xh[1], acc);
    acc = __hfma2(wh[2], xh[2], acc);
    acc = __hfma2(wh[3], xh[3], acc);
    return acc;
}
__device__ __forceinline__ float hsum2f(__half2 a) {
    float2 f = __half22float2(a);
    return f.x + f.y;
}
// dot of 8 fp32 weights (two float4) with 8 fp32 inputs (two float4)
__device__ __forceinline__ float dot8f(float4 wa, float4 wb, float4 xa, float4 xb) {
    float a = wa.x * xa.x;
    a = fmaf(wa.y, xa.y, a);
    a = fmaf(wa.z, xa.z, a); a = fmaf(wa.w, xa.w, a);
    a = fmaf(wb.x, xb.x, a); a = fmaf(wb.y, xb.y, a);
    a = fmaf(wb.z, xb.z, a); a = fmaf(wb.w, xb.w, a);
    return a;
}
// pack 8 consecutive fp32 -> uint4 of 8 fp16
__device__ __forceinline__ uint4 pack8(const float* __restrict__ s) {
    union { uint4 u; __half2 h[4]; } r;
    r.h[0] = __floats2half2_rn(__ldg(&s[0]), __ldg(&s[1]));
    r.h[1] = __floats2half2_rn(__ldg(&s[2]), __ldg(&s[3]));
    r.h[2] = __floats2half2_rn(__ldg(&s[4]), __ldg(&s[5]));
    r.h[3] = __floats2half2_rn(__ldg(&s[6]), __ldg(&s[7]));
    return r.u;
}

// ---------------- prep kernels ----------------
// build_x also converts Wsd -> fp16 (blocks 0..639, 64 elems each) so the
// launch count per call is 6 and ncu -s 5 -c 1 captures fargan_kernel.
__global__ void build_x_kernel(const float* __restrict__ feats,
                               const float* __restrict__ glob,
                               const float* __restrict__ Wsd)
{
    const int bt = blockIdx.x;
    const int b = bt / NFRAMES, t = bt % NFRAMES;
    const float* fb = feats + (long)b * NF * NFRAMES;
    for (int i = threadIdx.x; i < 192; i += blockDim.x)
        g_X[bt * 256 + i] = fb[i * NFRAMES + t];
    for (int i = threadIdx.x; i < 64; i += blockDim.x)
        g_X[bt * 256 + 192 + i] = glob[b * 64 + i];
    if (threadIdx.x == 0)
        g_period[bt] = (int)lrintf(fb[192 * NFRAMES + t]);
    if (bt < 640) {
        int i = bt * 64 + threadIdx.x;
        if (threadIdx.x < 64 && i < 128 * 320)
            g_hWsd[i] = __float2half(Wsd[i]);
    }
}

// C[M,N] = tanh(A[M,K] @ W[N,K]^T); tiles 64x64x64
__global__ __launch_bounds__(256)
void gemm_tanh_kernel(const float* __restrict__ Wt, int layer, int N, int K)
{
    const float* A = (layer == 0) ? g_X : (layer == 1) ? g_H1 : g_H2;
    float*       C = (layer == 0) ? g_H1 : (layer == 1) ? g_H2 : g_C;

    __shared__ float As[64][68];
    __shared__ float Ws[64][68];

    const int tid = threadIdx.x;
    const int m0 = blockIdx.y * 64, n0 = blockIdx.x * 64;
    const int lr = tid >> 2, lc = tid & 3;
    const int ty = tid >> 4, tx = tid & 15;

    float acc[4][4] = {};

    for (int k0 = 0; k0 < K; k0 += 64) {
        const float4* Arow = (const float4*)(A  + (long)(m0 + lr) * K + k0);
        const float4* Wrow = (const float4*)(Wt + (long)(n0 + lr) * K + k0);
        #pragma unroll
        for (int jj = 0; jj < 4; jj++) {
            float4 av = __ldg(&Arow[lc * 4 + jj]);
            float4 wv = __ldg(&Wrow[lc * 4 + jj]);
            int kk = lc * 16 + jj * 4;
            As[kk + 0][lr] = av.x; As[kk + 1][lr] = av.y;
            As[kk + 2][lr] = av.z; As[kk + 3][lr] = av.w;
            Ws[kk + 0][lr] = wv.x; Ws[kk + 1][lr] = wv.y;
            Ws[kk + 2][lr] = wv.z; Ws[kk + 3][lr] = wv.w;
        }
        __syncthreads();
        #pragma unroll
        for (int kk = 0; kk < 64; kk++) {
            float4 a = *(const float4*)&As[kk][ty * 4];
            float4 w = *(const float4*)&Ws[kk][tx * 4];
            acc[0][0] = fmaf(a.x, w.x, acc[0][0]); acc[0][1] = fmaf(a.x, w.y, acc[0][1]);
            acc[0][2] = fmaf(a.x, w.z, acc[0][2]); acc[0][3] = fmaf(a.x, w.w, acc[0][3]);
            acc[1][0] = fmaf(a.y, w.x, acc[1][0]); acc[1][1] = fmaf(a.y, w.y, acc[1][1]);
            acc[1][2] = fmaf(a.y, w.z, acc[1][2]); acc[1][3] = fmaf(a.y, w.w, acc[1][3]);
            acc[2][0] = fmaf(a.z, w.x, acc[2][0]); acc[2][1] = fmaf(a.z, w.y, acc[2][1]);
            acc[2][2] = fmaf(a.z, w.z, acc[2][2]); acc[2][3] = fmaf(a.z, w.w, acc[2][3]);
            acc[3][0] = fmaf(a.w, w.x, acc[3][0]); acc[3][1] = fmaf(a.w, w.y, acc[3][1]);
            acc[3][2] = fmaf(a.w, w.z, acc[3][2]); acc[3][3] = fmaf(a.w, w.w, acc[3][3]);
        }
        __syncthreads();
    }
    #pragma unroll
    for (int i = 0; i < 4; i++)
        #pragma unroll
        for (int j = 0; j < 4; j++)
            C[(long)(m0 + ty * 4 + i) * N + n0 + tx * 4 + j] = tanh_f(acc[i][j]);
}

// fwpre[bt][k][j] = Wfw[j,0:128] @ feat2s(bt,k) + Wfw[j,260:388] @ sfw(bt,k)
__global__ __launch_bounds__(256)
void fwpre_kernel(const float* __restrict__ Wfw)
{
    const int bt = blockIdx.x;
    const int t  = bt % NFRAMES;
    const int tid = threadIdx.x;
    __shared__ float sc[512], sp[512];
    for (int i = tid; i < 512; i += 256) {
        sc[i] = g_C[(long)bt * 512 + i];
        sp[i] = (t > 0) ? g_C[(long)(bt - 1) * 512 + i] : 0.f;
    }
    __syncthreads();
    const int p = tid & 3, row = tid >> 2;
    const float* wr = Wfw + row * 388;
    #pragma unroll
    for (int k = 0; k < 4; k++) {
        const float* sfw = (k == 0) ? sp : sc;
        const int ksf = (k == 0) ? 3 : (k - 1);
        float acc = 0.f;
        #pragma unroll 8
        for (int mm = 0; mm < 32; mm++) {
            int m = p * 32 + mm;
            acc = fmaf(__ldg(&wr[m]),       sc[4 * m + k],    acc);
            acc = fmaf(__ldg(&wr[260 + m]), sfw[4 * m + ksf], acc);
        }
        acc += __shfl_xor_sync(0xffffffffu, acc, 1);
        acc += __shfl_xor_sync(0xffffffffu, acc, 2);
        if (p == 0) g_fwpre[((long)bt * 4 + k) * 64 + row] = acc;
    }
}

// ---------------- serial recurrence ----------------

#define DYN_H16   (3 * 192 * 128 + 3 * 192 * 64)   // Wih x3 + Whh x3 = 110592 halfs
#define DYN_BYTES (DYN_H16 * 2)                    // 221184 B

__global__ __launch_bounds__(NTH, 1)
void fargan_kernel(const float* __restrict__ prev0,
                   const float* __restrict__ Wfw,     // (64,388)
                   const float* __restrict__ Wfw_g,   // (64,64)
                   const float* __restrict__ Wih1,    // (192,128)
                   const float* __restrict__ Whh1,    // (192,64)
                   const float* __restrict__ Wih2,
                   const float* __restrict__ Whh2,
                   const float* __restrict__ Wih3,
                   const float* __restrict__ Whh3,
                   const float* __restrict__ Wg1,     // (64,64)
                   const float* __restrict__ Wg2,
                   const float* __restrict__ Wg3,
                   const float* __restrict__ Wsg,     // (128,128)
                   const float* __restrict__ Wout,    // (64,128)
                   float* __restrict__ outp)          // (B, 25600)
{
    const int b   = blockIdx.x;
    const int tid = threadIdx.x;
    const int p   = tid & 7;        // 8 threads per row
    const int r0  = tid >> 3;       // 64 rows per pass

    extern __shared__ __half dynh[];
    __half* sWih = dynh;                 // 3 x 192 x 128
    __half* sWhh = dynh + 3 * 192 * 128; // 3 x 192 x 64

    __shared__ __align__(16) float  ring[LPREV];
    __shared__ __align__(16) float  st[2][3][S];     // fp32 recurrent state (double-buffered)
    __shared__ __align__(16) __half sth[2][3][S];    // half copy for Whh dots
    __shared__ __align__(16) float  subin[160];      // fp32 [prev_sub(64) | lookback(68) | zero pad]
    __shared__ __align__(16) float  fwv[S];          // fp32 (feeds fp32 gate dot)
    __shared__ __align__(16) __half xcath[2 * S];    // half GRU input [fw/o | psub]
    __shared__ __align__(16) __half skiph[5 * S];    // half [o1|o2|o3|fw|psub]
    __shared__ __align__(16) __half sdvh[2 * S];
    __shared__ __align__(16) __half sovh[2 * S];
    __shared__ __align__(16) float  fwp4[256];
    __shared__ int period_sh;

    // ---- one-time: stage Wih / Whh as fp16 into smem ----
    {
        const float* src[3] = { Wih1, Wih2, Wih3 };
        #pragma unroll
        for (int m = 0; m < 3; m++)
            for (int i = tid; i < 192 * 128; i += NTH)
                sWih[m * 192 * 128 + i] = __float2half(__ldg(&src[m][i]));
        const float* srh[3] = { Whh1, Whh2, Whh3 };
        #pragma unroll
        for (int m = 0; m < 3; m++)
            for (int i = tid; i < 192 * 64; i += NTH)
                sWhh[m * 192 * 64 + i] = __float2half(__ldg(&srh[m][i]));
    }

    // ---- persistent register weight caches ----
    // Wfw2 (cols [128,264) of Wfw) as 5 strided float4 chunks: chunk c = p + 8j,
    // covering subin float4-chunk c (window col 4c..4c+4). Zero beyond col 132.
    float4 rfw2v[5];
    #pragma unroll
    for (int j = 0; j < 5; j++) {
        int c = p + 8 * j;
        float e[4];
        #pragma unroll
        for (int q = 0; q < 4; q++) {
            int col = 4 * c + q;   // within 136.. window (subin idx)
            e[q] = (col < 132) ? __ldg(&Wfw[r0 * 388 + 128 + col]) : 0.f;
        }
        rfw2v[j] = make_float4(e[0], e[1], e[2], e[3]);
    }
    // gates (Wg1,Wg2,Wg3,Wfwg): fp32, row r0, cols [8p, 8p+8)  (32 regs)
    float4 rgf[4][2];
    {
        const float* gsrc[4] = { Wg1, Wg2, Wg3, Wfw_g };
        #pragma unroll
        for (int m = 0; m < 4; m++) {
            const float4* w = (const float4*)(gsrc[m] + r0 * 64 + 8 * p);
            rgf[m][0] = __ldg(&w[0]);
            rgf[m][1] = __ldg(&w[1]);
        }
    }
    // Wsg: 128x128 fp16, rows r0 and r0+64, chunks p and p+8
    uint4 rsgh[2][2];
    #pragma unroll
    for (int it = 0; it < 2; it++) {
        rsgh[it][0] = pack8(Wsg + (r0 + 64 * it) * 128 + 8 * p);
        rsgh[it][1] = pack8(Wsg + (r0 + 64 * it) * 128 + 8 * (p + 8));
    }
    // Wout: 64x128 fp16, row r0, chunks p and p+8
    uint4 routh[2];
    routh[0] = pack8(Wout + r0 * 128 + 8 * p);
    routh[1] = pack8(Wout + r0 * 128 + 8 * (p + 8));

    // Wsd chunk pointers: per part m (0..4), thread covers rows r0 / r0+64, cols [64m+8p, +8)
    const uint4* wsd0 = (const uint4*)(g_hWsd + r0 * 320) + p;         // + 8*m
    const uint4* wsd1 = (const uint4*)(g_hWsd + (r0 + 64) * 320) + p;  // + 8*m

    // ---- init state ----
    for (int i = tid; i < LPREV; i += NTH) ring[i] = prev0[b * LPREV + i];
    if (tid < 3 * S) {
        st[0][tid >> 6][tid & 63] = 0.f;
        sth[0][tid >> 6][tid & 63] = __half(0.f);
    }
    if (tid >= 132 && tid < 160) subin[tid] = 0.f;
    if (tid < 64) {   // initial psub seeding (stage L does it for later subframes)
        float v = prev0[b * LPREV + 448 + tid];
        subin[tid] = v;
        __half hv = __float2half(v);
        skiph[256 + tid] = hv;
        xcath[64 + tid] = hv;
    }
    int head = 0;
    int pb = 0;
    __syncthreads();

    const __half2 hz = __floats2half2_rn(0.f, 0.f);

    for (int tf = 0; tf < NFRAMES; tf++) {
        const int bt = b * NFRAMES + tf;
        // ---- frame top: stage fwpre for all 4 subframes + period ----
        if (tid < 256) fwp4[tid] = __ldg(&g_fwpre[(long)bt * 256 + tid]);
        if (tid == 0) period_sh = __ldg(&g_period[bt]);
        __syncthreads();
        const int period = period_sh;

        for (int k = 0; k < 4; k++) {
            float sd0 = 0.f, sd1 = 0.f;   // incremental Wsd @ skip accumulators

            // ---- A: lookback only (psub seeded by previous L / init) ----
            if (tid >= 64 && tid < 132) {
                int i = tid - 64;
                int idx = LPREV - period + i - 2;
                if (idx >= LPREV) idx -= period;
                subin[tid] = ring[(head + idx) & 511];
            }
            __syncthreads();

            // ---- B: fwraw = tanh(Wfw2 @ subin + fwpre)  [+ Wsd psub part]
            float fwreg;
            {
                uint4 w0 = __ldg(wsd0 + 32), w1 = __ldg(wsd1 + 32);   // part m=4 (psub)
                const float4* xs4 = (const float4*)subin;
                float a = 0.f;
                #pragma unroll
                for (int j = 0; j < 5; j++) {
                    float4 w = rfw2v[j];
                    float4 x = xs4[p + 8 * j];
                    a = fmaf(w.x, x.x, a); a = fmaf(w.y, x.y, a);
                    a = fmaf(w.z, x.z, a); a = fmaf(w.w, x.w, a);
                }
                fwreg = tanh_f(red8(a) + fwp4[k * 64 + r0]);
                if (p == 0) fwv[r0] = fwreg;
                uint4 xs = ((const uint4*)(skiph + 256))[p];
                sd0 += hsum2f(dot8hh(w0, xs, hz));
                sd1 += hsum2f(dot8hh(w1, xs, hz));
            }
            __syncthreads();

            // ---- C: fw = fwraw * sigm(Wfwg @ fwv)   (fp32 register gate)
            {
                const float4* x = (const float4*)fwv;
                float acc = red8(dot8f(rgf[3][0], rgf[3][1], x[2 * p], x[2 * p + 1]));
                fwreg = fwreg * sigm(acc);
                if (p == 0) {
                    __half hv = __float2half(fwreg);
                    skiph[192 + r0] = hv;
                    xcath[r0] = hv;
                }
            }
            __syncthreads();

            // ---- 3 x (GRU fused + GLU fused), half2 HFMA2 dots ----
            #pragma unroll
            for (int L = 0; L < 3; L++) {
                const __half* WI = sWih + L * 192 * 128;
                const __half* WH = sWhh + L * 192 * 64;
                const float* sto = st[pb][L];
                float* stn = st[pb ^ 1][L];
                __half* stnh = sth[pb ^ 1][L];
                float streg;
                {
                    // Wsd part for this stage: L=0 -> fw (m=3), L=1 -> o1 (m=0), L=2 -> o2 (m=1)
                    const int m = (L == 0) ? 3 : (L - 1);
                    uint4 w0 = __ldg(wsd0 + 8 * m), w1 = __ldg(wsd1 + 8 * m);

                    const uint4* xh = (const uint4*)xcath;
                    uint4 xa = xh[p], xb = xh[p + 8];
                    uint4 sv = ((const uint4*)sth[pb][L])[p];
                    float gi[3], gh[3];
                    #pragma unroll
                    for (int it = 0; it < 3; it++) {
                        const uint4* wi = (const uint4*)(WI + (r0 + (it << 6)) * 128);
                        __half2 acc = dot8hh(wi[p], xa, hz);
                        acc = dot8hh(wi[p + 8], xb, acc);
                        gi[it] = red8(hsum2f(acc));
                        const uint4* wh = (const uint4*)(WH + (r0 + (it << 6)) * 64);
                        gh[it] = red8(hsum2f(dot8hh(wh[p], sv, hz)));
                    }
                    float r = sigm(gi[0] + gh[0]);
                    float z = sigm(gi[1] + gh[1]);
                    float n = tanh_f(gi[2] + r * gh[2]);
                    streg = (1.f - z) * n + z * sto[r0];
                    if (p == 0) {
                        stn[r0] = streg;
                        stnh[r0] = __float2half(streg);
                    }

                    uint4 xm = ((const uint4*)(skiph + 64 * m))[p];
                    sd0 += hsum2f(dot8hh(w0, xm, hz));
                    sd1 += hsum2f(dot8hh(w1, xm, hz));
                }
                __syncthreads();
                {
                    const float4* x = (const float4*)stn;
                    float acc = red8(dot8f(rgf[L][0], rgf[L][1], x[2 * p], x[2 * p + 1]));
                    float v = streg * sigm(acc);
                    if (p == 0) {
                        __half hv = __float2half(v);
                        skiph[64 * L + r0] = hv;
                        if (L < 2) xcath[r0] = hv;
                    }
                }
                __syncthreads();
            }

            // ---- J (mini): add o3 part, finalize sdv ----
            float sdva[2];
            {
                uint4 w0 = __ldg(wsd0 + 16), w1 = __ldg(wsd1 + 16);   // part m=2 (o3)
                uint4 xm = ((const uint4*)(skiph + 128))[p];
                sd0 += hsum2f(dot8hh(w0, xm, hz));
                sd1 += hsum2f(dot8hh(w1, xm, hz));
                sdva[0] = tanh_f(red8(sd0));
                sdva[1] = tanh_f(red8(sd1));
                if (p == 0) {
                    sdvh[r0] = __float2half(sdva[0]);
                    sdvh[64 + r0] = __float2half(sdva[1]);
                }
            }
            __syncthreads();

            // ---- K: sov = sdv * sigm(Wsg @ sdv)   (register fp16, half2 dots)
            {
                const uint4* xh = (const uint4*)sdvh;
                uint4 xa = xh[p], xb = xh[p + 8];
                #pragma unroll
                for (int it = 0; it < 2; it++) {
                    __half2 acc = dot8hh(rsgh[it][0], xa, hz);
                    acc = dot8hh(rsgh[it][1], xb, acc);
                    float a = red8(hsum2f(acc));
                    if (p == 0) sovh[r0 + 64 * it] = __float2half(sdva[it] * sigm(a));
                }
            }
            __syncthreads();

            // ---- L: out = tanh(Wout @ sov); emit + ring update + psub seed ----
            {
                const uint4* xh = (const uint4*)sovh;
                __half2 acc = dot8hh(routh[0], xh[p], hz);
                acc = dot8hh(routh[1], xh[p + 8], acc);
                float out = tanh_f(red8(hsum2f(acc)));
                if (p == 0) {
                    outp[(long)b * (NFRAMES * 4 * S) + tf * (4 * S) + k * S + r0] = out;
                    ring[(head + r0) & 511] = out;
                    // seed next subframe's psub (out == next prev_sub)
                    subin[r0] = out;
                    __half hv = __float2half(out);
                    skiph[256 + r0] = hv;
                    xcath[64 + r0] = hv;
                }
            }
            head = (head + 64) & 511;
            pb ^= 1;
            __syncthreads();
        }
    }
}

extern "C" void kernel_launch(void* const* d_in, const int* in_sizes, int n_in,
                              void* d_out, int out_size)
{
    const float* feats = (const float*)d_in[0];
    const float* glob  = (const float*)d_in[1];
    const float* prev0 = (const float*)d_in[2];
    const float* Wc1   = (const float*)d_in[3];
    const float* Wc2   = (const float*)d_in[4];
    const float* Wc3   = (const float*)d_in[5];
    const float* Wfw   = (const float*)d_in[6];
    const float* Wfw_g = (const float*)d_in[7];
    const float* Wih1  = (const float*)d_in[8];
    const float* Whh1  = (const float*)d_in[9];
    const float* Wih2  = (const float*)d_in[10];
    const float* Whh2  = (const float*)d_in[11];
    const float* Wih3  = (const float*)d_in[12];
    const float* Whh3  = (const float*)d_in[13];
    const float* Wg1   = (const float*)d_in[14];
    const float* Wg2   = (const float*)d_in[15];
    const float* Wg3   = (const float*)d_in[16];
    const float* Wsg   = (const float*)d_in[17];
    const float* Wsd   = (const float*)d_in[18];
    const float* Wout  = (const float*)d_in[19];
    float* outp = (float*)d_out;

    static bool attr_set = false;
    if (!attr_set) {
        cudaFuncSetAttribute(fargan_kernel,
                             cudaFuncAttributeMaxDynamicSharedMemorySize, DYN_BYTES);
        attr_set = true;
    }

    build_x_kernel<<<NBT, 64>>>(feats, glob, Wsd);
    gemm_tanh_kernel<<<dim3(4, 100), 256>>>(Wc1, 0, 256, 256);
    gemm_tanh_kernel<<<dim3(4, 100), 256>>>(Wc2, 1, 256, 256);
    gemm_tanh_kernel<<<dim3(8, 100), 256>>>(Wc3, 2, 512, 256);
    fwpre_kernel<<<NBT, 256>>>(Wfw);
    fargan_kernel<<<BATCH, NTH, DYN_BYTES>>>(prev0,
                                  Wfw, Wfw_g,
                                  Wih1, Whh1, Wih2, Whh2, Wih3, Whh3,
                                  Wg1, Wg2, Wg3, Wsg, Wout, outp);
}